// round 10
// baseline (speedup 1.0000x reference)
#include <cuda_runtime.h>
#include <cuda_fp16.h>

typedef unsigned long long u64;
typedef unsigned int u32;

// ---------------- packed f32x2 primitives (sm_103a) ----------------
static __device__ __forceinline__ u64 pk(float lo, float hi) {
    u64 r; asm("mov.b64 %0, {%1, %2};" : "=l"(r) : "f"(lo), "f"(hi)); return r;
}
static __device__ __forceinline__ void upk(u64 v, float& lo, float& hi) {
    asm("mov.b64 {%0, %1}, %2;" : "=f"(lo), "=f"(hi) : "l"(v));
}
static __device__ __forceinline__ u64 ffma2(u64 a, u64 b, u64 c) {
    u64 d; asm("fma.rn.f32x2 %0, %1, %2, %3;" : "=l"(d) : "l"(a), "l"(b), "l"(c)); return d;
}

// single-MUFU tanh (MUFU.TANH)
static __device__ __forceinline__ float tanh_hw(float x) {
    float y; asm("tanh.approx.f32 %0, %1;" : "=f"(y) : "f"(x)); return y;
}

// tanh both halves of a packed fp32 pair, compress to fp16x2
static __device__ __forceinline__ u32 pack_tanh_h(u64 z) {
    float a, b; upk(z, a, b);
    float2 f; f.x = tanh_hw(a); f.y = tanh_hw(b);
    __half2 h = __float22half2_rn(f);
    return *reinterpret_cast<u32*>(&h);
}

// ---------------- shared-memory weight layout (plain floats, padded cols) ----------------
static constexpr int OW1  = 0;      // [2][32]
static constexpr int OB1  = 64;     // [32]
static constexpr int OW2  = 96;     // [30][32]
static constexpr int OB2  = 1056;   // [32]
static constexpr int OW3  = 1088;   // [30][32]
static constexpr int OB3  = 2048;   // [32]
static constexpr int OW4  = 2080;   // [30][8]
static constexpr int OB4  = 2320;   // [8]
static constexpr int OP1  = 2328;   // [2][16]
static constexpr int OPB1 = 2360;   // [16]
static constexpr int OP2  = 2376;   // [15][16]
static constexpr int OPB2 = 2616;   // [16]
static constexpr int OP3  = 2632;   // [15][16]
static constexpr int OPB3 = 2872;   // [16]
static constexpr int OP4  = 2888;   // [15][4]
static constexpr int OPB4 = 2948;   // [4]
static constexpr int SMW_TOTAL = 2952;  // floats = 11808 B

// ---- 16-col half-layer: fp16x2 acts in, 8 fp32-pair accs out; row stride 32 ----
template <int NI, int OFF>
static __device__ __forceinline__ void dense16_h(const float* __restrict__ Wm,
                                                 const float* __restrict__ Bs,
                                                 const u32* __restrict__ hA,
                                                 const u32* __restrict__ hB,
                                                 u64* __restrict__ aA,
                                                 u64* __restrict__ aB)
{
#pragma unroll
    for (int jp = 0; jp < 8; jp++) {
        float2 b = *(const float2*)(Bs + OFF + 2 * jp);
        u64 bp = pk(b.x, b.y);
        aA[jp] = bp; aB[jp] = bp;
    }
#pragma unroll
    for (int k = 0; k < NI; k++) {
        float2 fa = __half22float2(*reinterpret_cast<const __half2*>(&hA[k >> 1]));
        float2 fb = __half22float2(*reinterpret_cast<const __half2*>(&hB[k >> 1]));
        float av = (k & 1) ? fa.y : fa.x;
        float bv = (k & 1) ? fb.y : fb.x;
        u64 dA = pk(av, av);
        u64 dB = pk(bv, bv);
#pragma unroll
        for (int jq = 0; jq < 4; jq++) {
            float4 w = *(const float4*)(Wm + k * 32 + OFF + 4 * jq);
            u64 w01 = pk(w.x, w.y), w23 = pk(w.z, w.w);
            aA[2 * jq]     = ffma2(w01, dA, aA[2 * jq]);
            aA[2 * jq + 1] = ffma2(w23, dA, aA[2 * jq + 1]);
            aB[2 * jq]     = ffma2(w01, dB, aB[2 * jq]);
            aB[2 * jq + 1] = ffma2(w23, dB, aB[2 * jq + 1]);
        }
    }
}

// ---- 16-col half of the first layer (2 raw fp32 inputs); row stride 32 ----
template <int OFF>
static __device__ __forceinline__ void dense16_f2(const float* __restrict__ Wm,
                                                  const float* __restrict__ Bs,
                                                  float a0, float a1, float b0, float b1,
                                                  u64* __restrict__ aA,
                                                  u64* __restrict__ aB)
{
#pragma unroll
    for (int jp = 0; jp < 8; jp++) {
        float2 b = *(const float2*)(Bs + OFF + 2 * jp);
        u64 bp = pk(b.x, b.y);
        aA[jp] = bp; aB[jp] = bp;
    }
#pragma unroll
    for (int k = 0; k < 2; k++) {
        float av = k ? a1 : a0;
        float bv = k ? b1 : b0;
        u64 dA = pk(av, av);
        u64 dB = pk(bv, bv);
#pragma unroll
        for (int jq = 0; jq < 4; jq++) {
            float4 w = *(const float4*)(Wm + k * 32 + OFF + 4 * jq);
            u64 w01 = pk(w.x, w.y), w23 = pk(w.z, w.w);
            aA[2 * jq]     = ffma2(w01, dA, aA[2 * jq]);
            aA[2 * jq + 1] = ffma2(w23, dA, aA[2 * jq + 1]);
            aB[2 * jq]     = ffma2(w01, dB, aB[2 * jq]);
            aB[2 * jq + 1] = ffma2(w23, dB, aB[2 * jq + 1]);
        }
    }
}

// ---- final w-layer: 30 -> 8 cols, fp32-pair accs (row stride 8) ----
template <int NI>
static __device__ __forceinline__ void dense8_h(const float* __restrict__ Wm,
                                                const float* __restrict__ Bs,
                                                const u32* __restrict__ hA,
                                                const u32* __restrict__ hB,
                                                u64* __restrict__ aA,
                                                u64* __restrict__ aB)
{
#pragma unroll
    for (int jp = 0; jp < 4; jp++) {
        float2 b = *(const float2*)(Bs + 2 * jp);
        u64 bp = pk(b.x, b.y);
        aA[jp] = bp; aB[jp] = bp;
    }
#pragma unroll
    for (int k = 0; k < NI; k++) {
        float2 fa = __half22float2(*reinterpret_cast<const __half2*>(&hA[k >> 1]));
        float2 fb = __half22float2(*reinterpret_cast<const __half2*>(&hB[k >> 1]));
        float av = (k & 1) ? fa.y : fa.x;
        float bv = (k & 1) ? fb.y : fb.x;
        u64 dA = pk(av, av);
        u64 dB = pk(bv, bv);
#pragma unroll
        for (int jq = 0; jq < 2; jq++) {
            float4 w = *(const float4*)(Wm + k * 8 + 4 * jq);
            u64 w01 = pk(w.x, w.y), w23 = pk(w.z, w.w);
            aA[2 * jq]     = ffma2(w01, dA, aA[2 * jq]);
            aA[2 * jq + 1] = ffma2(w23, dA, aA[2 * jq + 1]);
            aB[2 * jq]     = ffma2(w01, dB, aB[2 * jq]);
            aB[2 * jq + 1] = ffma2(w23, dB, aB[2 * jq + 1]);
        }
    }
}

// fp32 dense for the phi-MLP (packed fp32 pair acts)
template <int NI, int NOP>
static __device__ __forceinline__ void dense_pp(const float* __restrict__ Wm,
                                                const float* __restrict__ Bs,
                                                const u64* __restrict__ hA,
                                                const u64* __restrict__ hB,
                                                u64* __restrict__ accA,
                                                u64* __restrict__ accB)
{
#pragma unroll
    for (int jp = 0; jp < NOP / 2; jp++) {
        float2 b = *(const float2*)(Bs + 2 * jp);
        u64 bp = pk(b.x, b.y);
        accA[jp] = bp; accB[jp] = bp;
    }
#pragma unroll
    for (int k = 0; k < NI; k++) {
        float alo, ahi; upk(hA[k >> 1], alo, ahi);
        float blo, bhi; upk(hB[k >> 1], blo, bhi);
        float av = (k & 1) ? ahi : alo;
        float bv = (k & 1) ? bhi : blo;
        u64 dA = pk(av, av);
        u64 dB = pk(bv, bv);
#pragma unroll
        for (int jq = 0; jq < NOP / 4; jq++) {
            float4 w = *(const float4*)(Wm + k * NOP + 4 * jq);
            u64 w01 = pk(w.x, w.y), w23 = pk(w.z, w.w);
            accA[2 * jq]     = ffma2(w01, dA, accA[2 * jq]);
            accA[2 * jq + 1] = ffma2(w23, dA, accA[2 * jq + 1]);
            accB[2 * jq]     = ffma2(w01, dB, accB[2 * jq]);
            accB[2 * jq + 1] = ffma2(w23, dB, accB[2 * jq + 1]);
        }
    }
}

template <int NOP>
static __device__ __forceinline__ void dense_f2(const float* __restrict__ Wm,
                                                const float* __restrict__ Bs,
                                                float a0, float a1, float b0, float b1,
                                                u64* __restrict__ accA,
                                                u64* __restrict__ accB)
{
#pragma unroll
    for (int jp = 0; jp < NOP / 2; jp++) {
        float2 b = *(const float2*)(Bs + 2 * jp);
        u64 bp = pk(b.x, b.y);
        accA[jp] = bp; accB[jp] = bp;
    }
#pragma unroll
    for (int k = 0; k < 2; k++) {
        float av = k ? a1 : a0;
        float bv = k ? b1 : b0;
        u64 dA = pk(av, av);
        u64 dB = pk(bv, bv);
#pragma unroll
        for (int jq = 0; jq < NOP / 4; jq++) {
            float4 w = *(const float4*)(Wm + k * NOP + 4 * jq);
            u64 w01 = pk(w.x, w.y), w23 = pk(w.z, w.w);
            accA[2 * jq]     = ffma2(w01, dA, accA[2 * jq]);
            accA[2 * jq + 1] = ffma2(w23, dA, accA[2 * jq + 1]);
            accB[2 * jq]     = ffma2(w01, dB, accB[2 * jq]);
            accB[2 * jq + 1] = ffma2(w23, dB, accB[2 * jq + 1]);
        }
    }
}

static __device__ __forceinline__ u64 tanh2(u64 v) {
    float a, b; upk(v, a, b);
    return pk(tanh_hw(a), tanh_hw(b));
}
template <int NN>
static __device__ __forceinline__ void tanh_all2(u64* a, u64* b) {
#pragma unroll
    for (int j = 0; j < NN; j++) { a[j] = tanh2(a[j]); b[j] = tanh2(b[j]); }
}

// compress 8 fp32-pairs (16 values) -> 8 fp16x2 slots of the act buffer
static __device__ __forceinline__ void compress8(const u64* zA, const u64* zB,
                                                 u32* hA, u32* hB) {
#pragma unroll
    for (int j = 0; j < 8; j++) { hA[j] = pack_tanh_h(zA[j]); hB[j] = pack_tanh_h(zB[j]); }
}

// ---------------- half-angle: sin(θ/2), cos(θ/2) from cosθ, sinθ ----------------
static __device__ __forceinline__ void halfang(float c, float sn, float& sh, float& ch) {
    ch = sqrtf(fmaxf(0.0f, 0.5f * (1.0f + c)));
    float sh_a = copysignf(sqrtf(fmaxf(0.0f, 0.5f * (1.0f - c))), sn);
    float sh_b = __fdividef(0.5f * sn, ch);
    sh = (ch > 0.1f) ? sh_b : sh_a;
}

// ---------------- per-point epilogue ----------------
static __device__ __forceinline__ float epilogue(
    float x0, float x1, float r, float cb, float sb,
    const float* wv, const float* pv, float lm)
{
    float s2  = fmaf(x0, x0, x1 * x1);
    float ri0 = rsqrtf(s2);
    float r0  = s2 * ri0;
    float c   = x0 * ri0, sn = x1 * ri0;
    float sh, ch; halfang(c, sn, sh, ch);
    float sq  = sqrtf(r0);
    float v0  = sq * sh;
    float v1  = r0 * sn;
    float v2  = (r0 * sq) * fmaf(sn, ch, c * sh);
    float shb, chb; halfang(cb, sb, shb, chb);
    float u0 = shb, u1 = sb, u2 = fmaf(sb, chb, cb * shb);
    float t  = fminf(fmaxf(fmaf(2.5f, r, -1.25f), 0.0f), 1.0f);
    float t3 = t * t * t;
    float yita = fmaf(fmaf(fmaf(-6.0f, t, 15.0f), t, -10.0f), t3, 1.0f);
    float rp = wv[0] + yita * wv[4]
             + fmaf(wv[5], yita, wv[1]) * v0
             + fmaf(wv[6], yita, wv[2]) * v1
             + fmaf(wv[7], yita, wv[3]) * v2;
    float s  = fmaf(pv[1], u0, fmaf(pv[2], u1, fmaf(pv[3], u2, pv[0])));
    float sp = s * yita * __powf(r, lm);
    return rp + sp;
}

// ---------------- kernel: 2 points/thread; chunked accs; 5 CTAs/SM target ----------------
__global__ void __launch_bounds__(128, 5)
mlp2d_kernel(const float* __restrict__ x,   const float* __restrict__ imv,
             const float* __restrict__ lmbd,
             const float* __restrict__ Ww1, const float* __restrict__ bw1,
             const float* __restrict__ Ww2, const float* __restrict__ bw2,
             const float* __restrict__ Ww3, const float* __restrict__ bw3,
             const float* __restrict__ Ww4, const float* __restrict__ bw4,
             const float* __restrict__ Wp1, const float* __restrict__ bp1,
             const float* __restrict__ Wp2, const float* __restrict__ bp2,
             const float* __restrict__ Wp3, const float* __restrict__ bp3,
             const float* __restrict__ Wp4, const float* __restrict__ bp4,
             float* __restrict__ out, int N)
{
    __shared__ alignas(16) float smw[SMW_TOTAL];
    __shared__ float scons[3];

    const int tid = threadIdx.x;
    {
        struct Seg { int off; int rows; int cols; int pad; };
        const Seg segs[16] = {
            {OW1, 2, 30, 32},  {OB1, 1, 30, 32},
            {OW2, 30, 30, 32}, {OB2, 1, 30, 32},
            {OW3, 30, 30, 32}, {OB3, 1, 30, 32},
            {OW4, 30, 8, 8},   {OB4, 1, 8, 8},
            {OP1, 2, 15, 16},  {OPB1, 1, 15, 16},
            {OP2, 15, 15, 16}, {OPB2, 1, 15, 16},
            {OP3, 15, 15, 16}, {OPB3, 1, 15, 16},
            {OP4, 15, 4, 4},   {OPB4, 1, 4, 4},
        };
        const float* srcs[16] = {Ww1, bw1, Ww2, bw2, Ww3, bw3, Ww4, bw4,
                                 Wp1, bp1, Wp2, bp2, Wp3, bp3, Wp4, bp4};
        for (int a = 0; a < 16; a++) {
            const Seg s = segs[a];
            const float* src = srcs[a];
            int n = s.rows * s.pad;
            for (int t = tid; t < n; t += 128) {
                int r = t / s.pad, c = t - r * s.pad;
                smw[s.off + t] = (c < s.cols) ? src[r * s.cols + c] : 0.0f;
            }
        }
        if (tid == 0) { scons[0] = imv[0]; scons[1] = imv[1]; scons[2] = lmbd[0]; }
    }
    __syncthreads();

    long long pair = (long long)blockIdx.x * 128 + tid;
    int i0 = (int)(2 * pair);
    if (i0 >= N) return;
    const bool full = (i0 + 1 < N);

    float xa0, xa1, xB0, xB1;
    if (full) {
        float4 p = *(const float4*)(x + 2 * (size_t)i0);
        xa0 = p.x; xa1 = p.y; xB0 = p.z; xB1 = p.w;
    } else {
        float2 p = *(const float2*)(x + 2 * (size_t)i0);
        xa0 = xB0 = p.x; xa1 = xB1 = p.y;
    }

    // ---- w-MLP: 2 -> 30 -> 30 -> 30 -> 8, fp16 acts, two 16-col passes/layer ----
    u64 ZA[8], ZB[8];            // chunked fp32 accumulators (8 pairs = 16 cols)
    u32 HA[16], HB[16];          // fp16x2 act buffer (32 slots)
    u32 GA[16], GB[16];          // next-layer act buffer

    // layer 1
    dense16_f2<0>(smw + OW1, smw + OB1, xa0, xa1, xB0, xB1, ZA, ZB);
    compress8(ZA, ZB, HA, HB);
    dense16_f2<16>(smw + OW1, smw + OB1, xa0, xa1, xB0, xB1, ZA, ZB);
    compress8(ZA, ZB, HA + 8, HB + 8);
    // layer 2
    dense16_h<30, 0>(smw + OW2, smw + OB2, HA, HB, ZA, ZB);
    compress8(ZA, ZB, GA, GB);
    dense16_h<30, 16>(smw + OW2, smw + OB2, HA, HB, ZA, ZB);
    compress8(ZA, ZB, GA + 8, GB + 8);
    // layer 3
    dense16_h<30, 0>(smw + OW3, smw + OB3, GA, GB, ZA, ZB);
    compress8(ZA, ZB, HA, HB);
    dense16_h<30, 16>(smw + OW3, smw + OB3, GA, GB, ZA, ZB);
    compress8(ZA, ZB, HA + 8, HB + 8);
    // layer 4 (30 -> 8)
    u64 WoA[4], WoB[4];
    dense8_h<30>(smw + OW4, smw + OB4, HA, HB, WoA, WoB);

    // ---- geometry about imv ----
    const float im0 = scons[0], im1 = scons[1], lm = scons[2];

    float dA0 = xa0 - im0, dA1 = xa1 - im1;
    float rsA = fmaf(dA0, dA0, dA1 * dA1);
    float riA = rsqrtf(rsA);
    float rA  = rsA * riA;
    float cbA = dA0 * riA, sbA = dA1 * riA;

    float dB0 = xB0 - im0, dB1 = xB1 - im1;
    float rsB = fmaf(dB0, dB0, dB1 * dB1);
    float riB = rsqrtf(rsB);
    float rB  = rsB * riB;
    float cbB = dB0 * riB, sbB = dB1 * riB;

    // ---- phi-MLP: 2 -> 15 -> 15 -> 15 -> 4, fp32 (reuses dead w-MLP regs) ----
    u64 PA[8], PB[8], QA[8], QB[8];
    dense_f2<16>(smw + OP1, smw + OPB1, cbA, sbA, cbB, sbB, PA, PB);
    tanh_all2<8>(PA, PB);
    dense_pp<15, 16>(smw + OP2, smw + OPB2, PA, PB, QA, QB);
    tanh_all2<8>(QA, QB);
    dense_pp<15, 16>(smw + OP3, smw + OPB3, QA, QB, PA, PB);
    tanh_all2<8>(PA, PB);
    u64 PhA[2], PhB[2];
    dense_pp<15, 4>(smw + OP4, smw + OPB4, PA, PB, PhA, PhB);

    // ---- unpack heads and finish per point ----
    float wA[8], wB[8], pA_[4], pB_[4];
#pragma unroll
    for (int j = 0; j < 4; j++) { upk(WoA[j], wA[2 * j], wA[2 * j + 1]);
                                  upk(WoB[j], wB[2 * j], wB[2 * j + 1]); }
#pragma unroll
    for (int j = 0; j < 2; j++) { upk(PhA[j], pA_[2 * j], pA_[2 * j + 1]);
                                  upk(PhB[j], pB_[2 * j], pB_[2 * j + 1]); }

    float eA = epilogue(xa0, xa1, rA, cbA, sbA, wA, pA_, lm);
    if (full) {
        float eB = epilogue(xB0, xB1, rB, cbB, sbB, wB, pB_, lm);
        *(float2*)(out + i0) = make_float2(eA, eB);
    } else {
        out[i0] = eA;
    }
}

extern "C" void kernel_launch(void* const* d_in, const int* in_sizes, int n_in,
                              void* d_out, int out_size)
{
    const float* x    = (const float*)d_in[0];
    const float* imv  = (const float*)d_in[1];
    const float* lmbd = (const float*)d_in[2];
    const float* Ww1  = (const float*)d_in[3];
    const float* bw1  = (const float*)d_in[4];
    const float* Ww2  = (const float*)d_in[5];
    const float* bw2  = (const float*)d_in[6];
    const float* Ww3  = (const float*)d_in[7];
    const float* bw3  = (const float*)d_in[8];
    const float* Ww4  = (const float*)d_in[9];
    const float* bw4  = (const float*)d_in[10];
    const float* Wp1  = (const float*)d_in[11];
    const float* bp1  = (const float*)d_in[12];
    const float* Wp2  = (const float*)d_in[13];
    const float* bp2  = (const float*)d_in[14];
    const float* Wp3  = (const float*)d_in[15];
    const float* bp3  = (const float*)d_in[16];
    const float* Wp4  = (const float*)d_in[17];
    const float* bp4  = (const float*)d_in[18];

    int N = out_size;
    long long pairs = ((long long)N + 1) / 2;
    int blocks = (int)((pairs + 127) / 128);

    mlp2d_kernel<<<blocks, 128>>>(x, imv, lmbd,
                                  Ww1, bw1, Ww2, bw2, Ww3, bw3, Ww4, bw4,
                                  Wp1, bp1, Wp2, bp2, Wp3, bp3, Wp4, bp4,
                                  (float*)d_out, N);
}

// round 11
// speedup vs baseline: 1.4434x; 1.4434x over previous
#include <cuda_runtime.h>
#include <cuda_fp16.h>

typedef unsigned long long u64;
typedef unsigned int u32;

// ---------------- packed f32x2 primitives (sm_103a) ----------------
static __device__ __forceinline__ u64 pk(float lo, float hi) {
    u64 r; asm("mov.b64 %0, {%1, %2};" : "=l"(r) : "f"(lo), "f"(hi)); return r;
}
static __device__ __forceinline__ void upk(u64 v, float& lo, float& hi) {
    asm("mov.b64 {%0, %1}, %2;" : "=f"(lo), "=f"(hi) : "l"(v));
}
static __device__ __forceinline__ u64 ffma2(u64 a, u64 b, u64 c) {
    u64 d; asm("fma.rn.f32x2 %0, %1, %2, %3;" : "=l"(d) : "l"(a), "l"(b), "l"(c)); return d;
}

// single-MUFU tanh (MUFU.TANH)
static __device__ __forceinline__ float tanh_hw(float x) {
    float y; asm("tanh.approx.f32 %0, %1;" : "=f"(y) : "f"(x)); return y;
}

// tanh both halves of a packed fp32 pair, compress to fp16x2
static __device__ __forceinline__ u32 pack_tanh_h(u64 z) {
    float a, b; upk(z, a, b);
    float2 f; f.x = tanh_hw(a); f.y = tanh_hw(b);
    __half2 h = __float22half2_rn(f);
    return *reinterpret_cast<u32*>(&h);
}

// ---------------- shared-memory weight layout (plain floats, padded cols) ----------------
static constexpr int OW1  = 0;      // [2][32]
static constexpr int OB1  = 64;     // [32]
static constexpr int OW2  = 96;     // [30][32]
static constexpr int OB2  = 1056;   // [32]
static constexpr int OW3  = 1088;   // [30][32]
static constexpr int OB3  = 2048;   // [32]
static constexpr int OW4  = 2080;   // [30][8]
static constexpr int OB4  = 2320;   // [8]
static constexpr int OP1  = 2328;   // [2][16]
static constexpr int OPB1 = 2360;   // [16]
static constexpr int OP2  = 2376;   // [15][16]
static constexpr int OPB2 = 2616;   // [16]
static constexpr int OP3  = 2632;   // [15][16]
static constexpr int OPB3 = 2872;   // [16]
static constexpr int OP4  = 2888;   // [15][4]
static constexpr int OPB4 = 2948;   // [4]
static constexpr int SMW_TOTAL = 2952;  // floats = 11808 B

// ---------------- dense layer: fp16x2 activations in, fp32-pair accs out ----------------
template <int NI, int NOP>
static __device__ __forceinline__ void dense_h(const float* __restrict__ Wm,
                                               const float* __restrict__ Bs,
                                               const u32* __restrict__ hA,
                                               const u32* __restrict__ hB,
                                               u64* __restrict__ accA,
                                               u64* __restrict__ accB)
{
#pragma unroll
    for (int jp = 0; jp < NOP / 2; jp++) {
        float2 b = *(const float2*)(Bs + 2 * jp);
        u64 bp = pk(b.x, b.y);
        accA[jp] = bp; accB[jp] = bp;
    }
#pragma unroll
    for (int k = 0; k < NI; k++) {
        float2 fa = __half22float2(*reinterpret_cast<const __half2*>(&hA[k >> 1]));
        float2 fb = __half22float2(*reinterpret_cast<const __half2*>(&hB[k >> 1]));
        float av = (k & 1) ? fa.y : fa.x;
        float bv = (k & 1) ? fb.y : fb.x;
        u64 dA = pk(av, av);
        u64 dB = pk(bv, bv);
#pragma unroll
        for (int jq = 0; jq < NOP / 4; jq++) {
            float4 w = *(const float4*)(Wm + k * NOP + 4 * jq);
            u64 w01 = pk(w.x, w.y), w23 = pk(w.z, w.w);
            accA[2 * jq]     = ffma2(w01, dA, accA[2 * jq]);
            accA[2 * jq + 1] = ffma2(w23, dA, accA[2 * jq + 1]);
            accB[2 * jq]     = ffma2(w01, dB, accB[2 * jq]);
            accB[2 * jq + 1] = ffma2(w23, dB, accB[2 * jq + 1]);
        }
    }
}

// first layer: two raw fp32 inputs per point
template <int NOP>
static __device__ __forceinline__ void dense_f2(const float* __restrict__ Wm,
                                                const float* __restrict__ Bs,
                                                float a0, float a1, float b0, float b1,
                                                u64* __restrict__ accA,
                                                u64* __restrict__ accB)
{
#pragma unroll
    for (int jp = 0; jp < NOP / 2; jp++) {
        float2 b = *(const float2*)(Bs + 2 * jp);
        u64 bp = pk(b.x, b.y);
        accA[jp] = bp; accB[jp] = bp;
    }
#pragma unroll
    for (int k = 0; k < 2; k++) {
        float av = k ? a1 : a0;
        float bv = k ? b1 : b0;
        u64 dA = pk(av, av);
        u64 dB = pk(bv, bv);
#pragma unroll
        for (int jq = 0; jq < NOP / 4; jq++) {
            float4 w = *(const float4*)(Wm + k * NOP + 4 * jq);
            u64 w01 = pk(w.x, w.y), w23 = pk(w.z, w.w);
            accA[2 * jq]     = ffma2(w01, dA, accA[2 * jq]);
            accA[2 * jq + 1] = ffma2(w23, dA, accA[2 * jq + 1]);
            accB[2 * jq]     = ffma2(w01, dB, accB[2 * jq]);
            accB[2 * jq + 1] = ffma2(w23, dB, accB[2 * jq + 1]);
        }
    }
}

// compress NP fp32-pairs -> NP fp16x2 slots (applies tanh)
template <int NP>
static __device__ __forceinline__ void act_compress_h(const u64* zA, const u64* zB,
                                                      u32* hA, u32* hB) {
#pragma unroll
    for (int j = 0; j < NP; j++) { hA[j] = pack_tanh_h(zA[j]); hB[j] = pack_tanh_h(zB[j]); }
}

// ---------------- half-angle: sin(θ/2), cos(θ/2) from cosθ, sinθ ----------------
static __device__ __forceinline__ void halfang(float c, float sn, float& sh, float& ch) {
    ch = sqrtf(fmaxf(0.0f, 0.5f * (1.0f + c)));
    float sh_a = copysignf(sqrtf(fmaxf(0.0f, 0.5f * (1.0f - c))), sn);
    float sh_b = __fdividef(0.5f * sn, ch);
    sh = (ch > 0.1f) ? sh_b : sh_a;
}

// ---------------- per-point epilogue ----------------
static __device__ __forceinline__ float epilogue(
    float x0, float x1, float r, float cb, float sb,
    const float* wv, const float* pv, float lm)
{
    float s2  = fmaf(x0, x0, x1 * x1);
    float ri0 = rsqrtf(s2);
    float r0  = s2 * ri0;
    float c   = x0 * ri0, sn = x1 * ri0;
    float sh, ch; halfang(c, sn, sh, ch);
    float sq  = sqrtf(r0);
    float v0  = sq * sh;
    float v1  = r0 * sn;
    float v2  = (r0 * sq) * fmaf(sn, ch, c * sh);
    float shb, chb; halfang(cb, sb, shb, chb);
    float u0 = shb, u1 = sb, u2 = fmaf(sb, chb, cb * shb);
    float t  = fminf(fmaxf(fmaf(2.5f, r, -1.25f), 0.0f), 1.0f);
    float t3 = t * t * t;
    float yita = fmaf(fmaf(fmaf(-6.0f, t, 15.0f), t, -10.0f), t3, 1.0f);
    float rp = wv[0] + yita * wv[4]
             + fmaf(wv[5], yita, wv[1]) * v0
             + fmaf(wv[6], yita, wv[2]) * v1
             + fmaf(wv[7], yita, wv[3]) * v2;
    float s  = fmaf(pv[1], u0, fmaf(pv[2], u1, fmaf(pv[3], u2, pv[0])));
    float sp = s * yita * __powf(r, lm);
    return rp + sp;
}

// ---------------- kernel: 2 points/thread; fp16 acts in BOTH MLPs; 5 CTAs/SM ----------------
__global__ void __launch_bounds__(128, 5)
mlp2d_kernel(const float* __restrict__ x,   const float* __restrict__ imv,
             const float* __restrict__ lmbd,
             const float* __restrict__ Ww1, const float* __restrict__ bw1,
             const float* __restrict__ Ww2, const float* __restrict__ bw2,
             const float* __restrict__ Ww3, const float* __restrict__ bw3,
             const float* __restrict__ Ww4, const float* __restrict__ bw4,
             const float* __restrict__ Wp1, const float* __restrict__ bp1,
             const float* __restrict__ Wp2, const float* __restrict__ bp2,
             const float* __restrict__ Wp3, const float* __restrict__ bp3,
             const float* __restrict__ Wp4, const float* __restrict__ bp4,
             float* __restrict__ out, int N)
{
    __shared__ alignas(16) float smw[SMW_TOTAL];
    __shared__ float scons[3];

    const int tid = threadIdx.x;
    {
        struct Seg { int off; int rows; int cols; int pad; };
        const Seg segs[16] = {
            {OW1, 2, 30, 32},  {OB1, 1, 30, 32},
            {OW2, 30, 30, 32}, {OB2, 1, 30, 32},
            {OW3, 30, 30, 32}, {OB3, 1, 30, 32},
            {OW4, 30, 8, 8},   {OB4, 1, 8, 8},
            {OP1, 2, 15, 16},  {OPB1, 1, 15, 16},
            {OP2, 15, 15, 16}, {OPB2, 1, 15, 16},
            {OP3, 15, 15, 16}, {OPB3, 1, 15, 16},
            {OP4, 15, 4, 4},   {OPB4, 1, 4, 4},
        };
        const float* srcs[16] = {Ww1, bw1, Ww2, bw2, Ww3, bw3, Ww4, bw4,
                                 Wp1, bp1, Wp2, bp2, Wp3, bp3, Wp4, bp4};
        for (int a = 0; a < 16; a++) {
            const Seg s = segs[a];
            const float* src = srcs[a];
            int n = s.rows * s.pad;
            for (int t = tid; t < n; t += 128) {
                int r = t / s.pad, c = t - r * s.pad;
                smw[s.off + t] = (c < s.cols) ? src[r * s.cols + c] : 0.0f;
            }
        }
        if (tid == 0) { scons[0] = imv[0]; scons[1] = imv[1]; scons[2] = lmbd[0]; }
    }
    __syncthreads();

    long long pair = (long long)blockIdx.x * 128 + tid;
    int i0 = (int)(2 * pair);
    if (i0 >= N) return;
    const bool full = (i0 + 1 < N);

    float xa0, xa1, xB0, xB1;
    if (full) {
        float4 p = *(const float4*)(x + 2 * (size_t)i0);
        xa0 = p.x; xa1 = p.y; xB0 = p.z; xB1 = p.w;
    } else {
        float2 p = *(const float2*)(x + 2 * (size_t)i0);
        xa0 = xB0 = p.x; xa1 = xB1 = p.y;
    }

    // ---- w-MLP: 2 -> 30 -> 30 -> 30 -> 8, fp16-compressed activations ----
    u64 ZA[16], ZB[16];          // fp32 pre-activation pairs (accumulators)
    u32 HA[16], HB[16];          // fp16x2 activations

    dense_f2<32>(smw + OW1, smw + OB1, xa0, xa1, xB0, xB1, ZA, ZB);
    act_compress_h<16>(ZA, ZB, HA, HB);
    dense_h<30, 32>(smw + OW2, smw + OB2, HA, HB, ZA, ZB);
    act_compress_h<16>(ZA, ZB, HA, HB);
    dense_h<30, 32>(smw + OW3, smw + OB3, HA, HB, ZA, ZB);
    act_compress_h<16>(ZA, ZB, HA, HB);
    u64 WoA[4], WoB[4];
    dense_h<30, 8>(smw + OW4, smw + OB4, HA, HB, WoA, WoB);

    // ---- geometry about imv ----
    const float im0 = scons[0], im1 = scons[1], lm = scons[2];

    float dA0 = xa0 - im0, dA1 = xa1 - im1;
    float rsA = fmaf(dA0, dA0, dA1 * dA1);
    float riA = rsqrtf(rsA);
    float rA  = rsA * riA;
    float cbA = dA0 * riA, sbA = dA1 * riA;

    float dB0 = xB0 - im0, dB1 = xB1 - im1;
    float rsB = fmaf(dB0, dB0, dB1 * dB1);
    float riB = rsqrtf(rsB);
    float rB  = rsB * riB;
    float cbB = dB0 * riB, sbB = dB1 * riB;

    // ---- phi-MLP: 2 -> 15 -> 15 -> 15 -> 4, fp16-compressed acts (reuses regs) ----
    u64 PZ_A[8], PZ_B[8];
    u32 PH_A[8], PH_B[8];
    dense_f2<16>(smw + OP1, smw + OPB1, cbA, sbA, cbB, sbB, PZ_A, PZ_B);
    act_compress_h<8>(PZ_A, PZ_B, PH_A, PH_B);
    dense_h<15, 16>(smw + OP2, smw + OPB2, PH_A, PH_B, PZ_A, PZ_B);
    act_compress_h<8>(PZ_A, PZ_B, PH_A, PH_B);
    dense_h<15, 16>(smw + OP3, smw + OPB3, PH_A, PH_B, PZ_A, PZ_B);
    act_compress_h<8>(PZ_A, PZ_B, PH_A, PH_B);
    u64 PhA[2], PhB[2];
    dense_h<15, 4>(smw + OP4, smw + OPB4, PH_A, PH_B, PhA, PhB);

    // ---- unpack heads and finish per point ----
    float wA[8], wB[8], pA_[4], pB_[4];
#pragma unroll
    for (int j = 0; j < 4; j++) { upk(WoA[j], wA[2 * j], wA[2 * j + 1]);
                                  upk(WoB[j], wB[2 * j], wB[2 * j + 1]); }
#pragma unroll
    for (int j = 0; j < 2; j++) { upk(PhA[j], pA_[2 * j], pA_[2 * j + 1]);
                                  upk(PhB[j], pB_[2 * j], pB_[2 * j + 1]); }

    float eA = epilogue(xa0, xa1, rA, cbA, sbA, wA, pA_, lm);
    if (full) {
        float eB = epilogue(xB0, xB1, rB, cbB, sbB, wB, pB_, lm);
        *(float2*)(out + i0) = make_float2(eA, eB);
    } else {
        out[i0] = eA;
    }
}

extern "C" void kernel_launch(void* const* d_in, const int* in_sizes, int n_in,
                              void* d_out, int out_size)
{
    const float* x    = (const float*)d_in[0];
    const float* imv  = (const float*)d_in[1];
    const float* lmbd = (const float*)d_in[2];
    const float* Ww1  = (const float*)d_in[3];
    const float* bw1  = (const float*)d_in[4];
    const float* Ww2  = (const float*)d_in[5];
    const float* bw2  = (const float*)d_in[6];
    const float* Ww3  = (const float*)d_in[7];
    const float* bw3  = (const float*)d_in[8];
    const float* Ww4  = (const float*)d_in[9];
    const float* bw4  = (const float*)d_in[10];
    const float* Wp1  = (const float*)d_in[11];
    const float* bp1  = (const float*)d_in[12];
    const float* Wp2  = (const float*)d_in[13];
    const float* bp2  = (const float*)d_in[14];
    const float* Wp3  = (const float*)d_in[15];
    const float* bp3  = (const float*)d_in[16];
    const float* Wp4  = (const float*)d_in[17];
    const float* bp4  = (const float*)d_in[18];

    int N = out_size;
    long long pairs = ((long long)N + 1) / 2;
    int blocks = (int)((pairs + 127) / 128);

    mlp2d_kernel<<<blocks, 128>>>(x, imv, lmbd,
                                  Ww1, bw1, Ww2, bw2, Ww3, bw3, Ww4, bw4,
                                  Wp1, bp1, Wp2, bp2, Wp3, bp3, Wp4, bp4,
                                  (float*)d_out, N);
}

// round 12
// speedup vs baseline: 3.0379x; 2.1048x over previous
#include <cuda_runtime.h>
#include <cuda_fp16.h>

typedef unsigned long long u64;
typedef unsigned int u32;

// ---------------- scalar helpers ----------------
static __device__ __forceinline__ float tanh_hw(float x) {
    float y; asm("tanh.approx.f32 %0, %1;" : "=f"(y) : "f"(x)); return y;
}
static __device__ __forceinline__ u32 f22h2(float lo, float hi) {
    __half2 h = __floats2half2_rn(lo, hi);
    return *reinterpret_cast<u32*>(&h);
}
// tanh + pack to f16x2 (low = first arg)
static __device__ __forceinline__ u32 tp(float a, float b) {
    return f22h2(tanh_hw(a), tanh_hw(b));
}

// ---------------- mma.m16n8k16 f16*f16 -> f32 ----------------
static __device__ __forceinline__ void mma_16816(float c[4], const u32 a[4], u32 b0, u32 b1) {
    asm volatile(
        "mma.sync.aligned.m16n8k16.row.col.f32.f16.f16.f32 "
        "{%0,%1,%2,%3}, {%4,%5,%6,%7}, {%8,%9}, {%0,%1,%2,%3};"
        : "+f"(c[0]), "+f"(c[1]), "+f"(c[2]), "+f"(c[3])
        : "r"(a[0]), "r"(a[1]), "r"(a[2]), "r"(a[3]), "r"(b0), "r"(b1));
}

// generic layer: C[NTILES][4] += A[KTILES] x B(Wt)   (Wt layout: [n][KP] halves)
template <int NTILES, int KTILES>
static __device__ __forceinline__ void mma_layer(
    float (*c)[4], const u32 (*a)[4],
    const __half* wt, int KP, int g, int qi)
{
#pragma unroll
    for (int nt = 0; nt < NTILES; nt++) {
#pragma unroll
        for (int kt = 0; kt < KTILES; kt++) {
            const __half* base = wt + (nt * 8 + g) * KP + kt * 16 + 2 * qi;
            u32 b0 = *(const u32*)base;
            u32 b1 = *(const u32*)(base + 8);
            mma_16816(c[nt], a[kt], b0, b1);
        }
    }
}

template <int NTILES>
static __device__ __forceinline__ void bias_init(float (*c)[4], const float* bias, int qi) {
#pragma unroll
    for (int nt = 0; nt < NTILES; nt++) {
        float2 bb = *(const float2*)(bias + nt * 8 + 2 * qi);
        c[nt][0] = bb.x; c[nt][1] = bb.y; c[nt][2] = bb.x; c[nt][3] = bb.y;
    }
}

// C (2*KTILES N-tiles) --tanh+cvt--> A (KTILES K-tiles). Fragment-layout identity:
// a0=(g,2i|2i+1), a1=(g+8,..), a2/a3 = next N-tile.
template <int KTILES>
static __device__ __forceinline__ void act_trans(u32 (*a)[4], const float (*c)[4]) {
#pragma unroll
    for (int kt = 0; kt < KTILES; kt++) {
        a[kt][0] = tp(c[2 * kt][0],     c[2 * kt][1]);
        a[kt][1] = tp(c[2 * kt][2],     c[2 * kt][3]);
        a[kt][2] = tp(c[2 * kt + 1][0], c[2 * kt + 1][1]);
        a[kt][3] = tp(c[2 * kt + 1][2], c[2 * kt + 1][3]);
    }
}

// ---------------- smem layout ----------------
// Wt segments (halves), all [n][KP], padded with zeros:
static constexpr int SW1 = 0;     // [32][16]
static constexpr int SW2 = 512;   // [32][32]
static constexpr int SW3 = 1536;  // [32][32]
static constexpr int SW4 = 2560;  // [8][32]
static constexpr int SP1 = 2816;  // [16][16]
static constexpr int SP2 = 3072;  // [16][16]
static constexpr int SP3 = 3328;  // [16][16]
static constexpr int SP4 = 3584;  // [8][16]
static constexpr int WT_TOTAL = 3712;
// bias offsets (floats)
static constexpr int BW1 = 0, BW2 = 32, BW3 = 64, BW4 = 96;
static constexpr int BP1 = 104, BP2 = 120, BP3 = 136, BP4 = 152;
static constexpr int B_TOTAL = 160;
static constexpr int HSTRIDE = 13;   // head buffer row stride (pad for banks)

// ---------------- half-angle + epilogue (unchanged scalar path) ----------------
static __device__ __forceinline__ void halfang(float c, float sn, float& sh, float& ch) {
    ch = sqrtf(fmaxf(0.0f, 0.5f * (1.0f + c)));
    float sh_a = copysignf(sqrtf(fmaxf(0.0f, 0.5f * (1.0f - c))), sn);
    float sh_b = __fdividef(0.5f * sn, ch);
    sh = (ch > 0.1f) ? sh_b : sh_a;
}
static __device__ __forceinline__ float epilogue(
    float x0, float x1, float r, float cb, float sb,
    const float* wv, const float* pv, float lm)
{
    float s2  = fmaf(x0, x0, x1 * x1);
    float ri0 = rsqrtf(s2);
    float r0  = s2 * ri0;
    float c   = x0 * ri0, sn = x1 * ri0;
    float sh, ch; halfang(c, sn, sh, ch);
    float sq  = sqrtf(r0);
    float v0  = sq * sh;
    float v1  = r0 * sn;
    float v2  = (r0 * sq) * fmaf(sn, ch, c * sh);
    float shb, chb; halfang(cb, sb, shb, chb);
    float u0 = shb, u1 = sb, u2 = fmaf(sb, chb, cb * shb);
    float t  = fminf(fmaxf(fmaf(2.5f, r, -1.25f), 0.0f), 1.0f);
    float t3 = t * t * t;
    float yita = fmaf(fmaf(fmaf(-6.0f, t, 15.0f), t, -10.0f), t3, 1.0f);
    float rp = wv[0] + yita * wv[4]
             + fmaf(wv[5], yita, wv[1]) * v0
             + fmaf(wv[6], yita, wv[2]) * v1
             + fmaf(wv[7], yita, wv[3]) * v2;
    float s  = fmaf(pv[1], u0, fmaf(pv[2], u1, fmaf(pv[3], u2, pv[0])));
    float sp = s * yita * __powf(r, lm);
    return rp + sp;
}

// ---------------- kernel: 64 points per warp via HMMA ----------------
__global__ void __launch_bounds__(128)
mlp2d_kernel(const float* __restrict__ x,   const float* __restrict__ imv,
             const float* __restrict__ lmbd,
             const float* __restrict__ Ww1, const float* __restrict__ bw1,
             const float* __restrict__ Ww2, const float* __restrict__ bw2,
             const float* __restrict__ Ww3, const float* __restrict__ bw3,
             const float* __restrict__ Ww4, const float* __restrict__ bw4,
             const float* __restrict__ Wp1, const float* __restrict__ bp1,
             const float* __restrict__ Wp2, const float* __restrict__ bp2,
             const float* __restrict__ Wp3, const float* __restrict__ bp3,
             const float* __restrict__ Wp4, const float* __restrict__ bp4,
             float* __restrict__ out, long long N)
{
    __shared__ alignas(16) __half WT[WT_TOTAL];
    __shared__ alignas(16) float  BIAS[B_TOTAL];
    __shared__ alignas(16) float  XF[4][256];            // per warp: X[64][2] | F[64][2]
    __shared__ alignas(16) float  HB[4][64 * HSTRIDE];   // per warp head buffer
    __shared__ float scons[3];

    const int tid = threadIdx.x;

    // ---- cooperative weight fill: transpose to [n][KP] fp16, zero-padded ----
    {
        struct WSeg { const float* src; int off, KP, NP, KI, NO; };
        const WSeg ws[8] = {
            {Ww1, SW1, 16, 32, 2, 30}, {Ww2, SW2, 32, 32, 30, 30},
            {Ww3, SW3, 32, 32, 30, 30}, {Ww4, SW4, 32, 8, 30, 8},
            {Wp1, SP1, 16, 16, 2, 15}, {Wp2, SP2, 16, 16, 15, 15},
            {Wp3, SP3, 16, 16, 15, 15}, {Wp4, SP4, 16, 8, 15, 4},
        };
        for (int a = 0; a < 8; a++) {
            const WSeg s = ws[a];
            int n_el = s.NP * s.KP;
            for (int t = tid; t < n_el; t += 128) {
                int n = t / s.KP, k = t - n * s.KP;
                float v = (k < s.KI && n < s.NO) ? s.src[k * s.NO + n] : 0.0f;
                WT[s.off + t] = __float2half(v);
            }
        }
        struct BSeg { const float* src; int off, len, real; };
        const BSeg bs[8] = {
            {bw1, BW1, 32, 30}, {bw2, BW2, 32, 30}, {bw3, BW3, 32, 30}, {bw4, BW4, 8, 8},
            {bp1, BP1, 16, 15}, {bp2, BP2, 16, 15}, {bp3, BP3, 16, 15}, {bp4, BP4, 8, 4},
        };
        for (int a = 0; a < 8; a++) {
            const BSeg s = bs[a];
            for (int t = tid; t < s.len; t += 128)
                BIAS[s.off + t] = (t < s.real) ? s.src[t] : 0.0f;
        }
        if (tid == 0) { scons[0] = imv[0]; scons[1] = imv[1]; scons[2] = lmbd[0]; }
    }
    __syncthreads();

    const int lane = tid & 31;
    const int warp = tid >> 5;
    const int g = lane >> 2;        // groupID (row within tile)
    const int qi = lane & 3;        // thread-in-group (col pair selector)

    long long warpBase = ((long long)blockIdx.x * 4 + warp) * 64;
    if (warpBase >= N) return;

    // ---- load my 2 points, compute geometry, stage to smem ----
    long long i0 = warpBase + 2 * lane;
    long long iload = (i0 + 1 < N) ? i0 : (N - 2);
    float4 p = *(const float4*)(x + 2 * (size_t)iload);
    float xa0 = p.x, xa1 = p.y, xb0 = p.z, xb1 = p.w;

    const float im0 = scons[0], im1 = scons[1], lm = scons[2];
    float dA0 = xa0 - im0, dA1 = xa1 - im1;
    float rsA = fmaf(dA0, dA0, dA1 * dA1);
    float riA = rsqrtf(rsA);
    float rA = rsA * riA, cbA = dA0 * riA, sbA = dA1 * riA;
    float dB0 = xb0 - im0, dB1 = xb1 - im1;
    float rsB = fmaf(dB0, dB0, dB1 * dB1);
    float riB = rsqrtf(rsB);
    float rB = rsB * riB, cbB = dB0 * riB, sbB = dB1 * riB;

    float* Xb = &XF[warp][0];
    float* Fb = &XF[warp][128];
    float* Hb = &HB[warp][0];
    {
        int r0 = 2 * lane, r1 = r0 + 1;
        Xb[2 * r0] = xa0; Xb[2 * r0 + 1] = xa1;
        Xb[2 * r1] = xb0; Xb[2 * r1 + 1] = xb1;
        Fb[2 * r0] = cbA; Fb[2 * r0 + 1] = sbA;
        Fb[2 * r1] = cbB; Fb[2 * r1 + 1] = sbB;
    }
    __syncwarp();

    // ---- per-M-tile network (16 points per iteration; tiles independent) ----
#pragma unroll 1
    for (int mt = 0; mt < 4; mt++) {
        int row0 = mt * 16 + g, row1 = row0 + 8;

        // ===== w-MLP: 2 -> 30 -> 30 -> 30 -> 8 =====
        u32 aL1[1][4];
        aL1[0][0] = (qi == 0) ? f22h2(Xb[2 * row0], Xb[2 * row0 + 1]) : 0u;
        aL1[0][1] = (qi == 0) ? f22h2(Xb[2 * row1], Xb[2 * row1 + 1]) : 0u;
        aL1[0][2] = 0u; aL1[0][3] = 0u;

        float cw[4][4];
        bias_init<4>(cw, BIAS + BW1, qi);
        mma_layer<4, 1>(cw, aL1, WT + SW1, 16, g, qi);

        u32 aw[2][4];
        act_trans<2>(aw, cw);
        bias_init<4>(cw, BIAS + BW2, qi);
        mma_layer<4, 2>(cw, aw, WT + SW2, 32, g, qi);

        act_trans<2>(aw, cw);
        bias_init<4>(cw, BIAS + BW3, qi);
        mma_layer<4, 2>(cw, aw, WT + SW3, 32, g, qi);

        act_trans<2>(aw, cw);
        float c4[1][4];
        bias_init<1>(c4, BIAS + BW4, qi);
        mma_layer<1, 2>(c4, aw, WT + SW4, 32, g, qi);

        Hb[row0 * HSTRIDE + 2 * qi]     = c4[0][0];
        Hb[row0 * HSTRIDE + 2 * qi + 1] = c4[0][1];
        Hb[row1 * HSTRIDE + 2 * qi]     = c4[0][2];
        Hb[row1 * HSTRIDE + 2 * qi + 1] = c4[0][3];

        // ===== phi-MLP: 2 -> 15 -> 15 -> 15 -> 4 =====
        u32 aP1[1][4];
        aP1[0][0] = (qi == 0) ? f22h2(Fb[2 * row0], Fb[2 * row0 + 1]) : 0u;
        aP1[0][1] = (qi == 0) ? f22h2(Fb[2 * row1], Fb[2 * row1 + 1]) : 0u;
        aP1[0][2] = 0u; aP1[0][3] = 0u;

        float cp[2][4];
        bias_init<2>(cp, BIAS + BP1, qi);
        mma_layer<2, 1>(cp, aP1, WT + SP1, 16, g, qi);

        u32 ap[1][4];
        act_trans<1>(ap, cp);
        bias_init<2>(cp, BIAS + BP2, qi);
        mma_layer<2, 1>(cp, ap, WT + SP2, 16, g, qi);

        act_trans<1>(ap, cp);
        bias_init<2>(cp, BIAS + BP3, qi);
        mma_layer<2, 1>(cp, ap, WT + SP3, 16, g, qi);

        act_trans<1>(ap, cp);
        float cp4[1][4];
        bias_init<1>(cp4, BIAS + BP4, qi);
        mma_layer<1, 1>(cp4, ap, WT + SP4, 16, g, qi);

        if (qi < 2) {
            Hb[row0 * HSTRIDE + 8 + 2 * qi]     = cp4[0][0];
            Hb[row0 * HSTRIDE + 8 + 2 * qi + 1] = cp4[0][1];
            Hb[row1 * HSTRIDE + 8 + 2 * qi]     = cp4[0][2];
            Hb[row1 * HSTRIDE + 8 + 2 * qi + 1] = cp4[0][3];
        }
    }
    __syncwarp();

    // ---- epilogue on my own 2 points ----
    {
        int r0 = 2 * lane, r1 = r0 + 1;
        float wv[8], pv[4];
#pragma unroll
        for (int j = 0; j < 8; j++) wv[j] = Hb[r0 * HSTRIDE + j];
#pragma unroll
        for (int j = 0; j < 4; j++) pv[j] = Hb[r0 * HSTRIDE + 8 + j];
        float eA = epilogue(xa0, xa1, rA, cbA, sbA, wv, pv, lm);

#pragma unroll
        for (int j = 0; j < 8; j++) wv[j] = Hb[r1 * HSTRIDE + j];
#pragma unroll
        for (int j = 0; j < 4; j++) pv[j] = Hb[r1 * HSTRIDE + 8 + j];
        float eB = epilogue(xb0, xb1, rB, cbB, sbB, wv, pv, lm);

        if (i0 + 1 < N) {
            *(float2*)(out + i0) = make_float2(eA, eB);
        } else if (i0 < N) {
            out[i0] = eA;
        }
    }
}

extern "C" void kernel_launch(void* const* d_in, const int* in_sizes, int n_in,
                              void* d_out, int out_size)
{
    const float* x    = (const float*)d_in[0];
    const float* imv  = (const float*)d_in[1];
    const float* lmbd = (const float*)d_in[2];
    const float* Ww1  = (const float*)d_in[3];
    const float* bw1  = (const float*)d_in[4];
    const float* Ww2  = (const float*)d_in[5];
    const float* bw2  = (const float*)d_in[6];
    const float* Ww3  = (const float*)d_in[7];
    const float* bw3  = (const float*)d_in[8];
    const float* Ww4  = (const float*)d_in[9];
    const float* bw4  = (const float*)d_in[10];
    const float* Wp1  = (const float*)d_in[11];
    const float* bp1  = (const float*)d_in[12];
    const float* Wp2  = (const float*)d_in[13];
    const float* bp2  = (const float*)d_in[14];
    const float* Wp3  = (const float*)d_in[15];
    const float* bp3  = (const float*)d_in[16];
    const float* Wp4  = (const float*)d_in[17];
    const float* bp4  = (const float*)d_in[18];

    long long N = out_size;
    long long blocks = (N + 255) / 256;   // 4 warps x 64 points per block

    mlp2d_kernel<<<(int)blocks, 128>>>(x, imv, lmbd,
                                       Ww1, bw1, Ww2, bw2, Ww3, bw3, Ww4, bw4,
                                       Wp1, bp1, Wp2, bp2, Wp3, bp3, Wp4, bp4,
                                       (float*)d_out, N);
}